// round 1
// baseline (speedup 1.0000x reference)
#include <cuda_runtime.h>
#include <math.h>

#define SL 36
#define TL 20
#define SENT (1u << 19)
#define TENT (1u << 17)
#define SMASK (SENT - 1u)
#define TMASK (TENT - 1u)
#define HID 128
#define ENC 112          // (SL+TL)*2
#define NSLOT (SL + TL)  // 56
#define P 8              // points per block
#define NT 128           // threads per block

// ---------------------------------------------------------------------------
// block-wide sum reduction of NV values (each of the 128 threads contributes
// vals[v]); on return every thread holds the block total in vals[v].
// red must be shared float[NV][4].
// ---------------------------------------------------------------------------
template <int NV>
__device__ __forceinline__ void block_reduce(float* vals, float (*red)[4], int tid) {
    int lane = tid & 31;
    int wid  = tid >> 5;
#pragma unroll
    for (int v = 0; v < NV; v++) {
        float x = vals[v];
#pragma unroll
        for (int o = 16; o > 0; o >>= 1)
            x += __shfl_xor_sync(0xffffffffu, x, o);
        if (lane == 0) red[v][wid] = x;
    }
    __syncthreads();
#pragma unroll
    for (int v = 0; v < NV; v++)
        vals[v] = (red[v][0] + red[v][1]) + (red[v][2] + red[v][3]);
    __syncthreads();  // guard red[] before reuse
}

__global__ __launch_bounds__(NT)
void earth4d_fused_kernel(const float4* __restrict__ coords,
                          const float2* __restrict__ stab,   // [SL][2^19] of float2
                          const float2* __restrict__ ttab,   // [TL][2^17] of float2
                          const float*  __restrict__ w1,     // [112][128]
                          const float*  __restrict__ b1,
                          const float*  __restrict__ g1,
                          const float*  __restrict__ beta1,
                          const float*  __restrict__ w2,     // [128][128]
                          const float*  __restrict__ b2,
                          const float*  __restrict__ g2,
                          const float*  __restrict__ beta2,
                          const float*  __restrict__ w3,     // [128][1]
                          const float*  __restrict__ b3,
                          float* __restrict__ out, int B)
{
    __shared__ float ress[SL];
    __shared__ float rest[TL];
    __shared__ __align__(16) float featsm[ENC][P];
    __shared__ __align__(16) float h1sm[HID][P];
    __shared__ float red[2 * P][4];

    const int tid = threadIdx.x;

    // Per-level resolutions. Must reproduce fp32 floor(16 * pow(1.38f, l)):
    // double pow of the *fp32* base gives the correctly-rounded fp32 power.
    if (tid < SL) {
        float pw = (float)pow((double)1.38f, (double)tid);
        ress[tid] = floorf(16.0f * pw);
    } else if (tid < SL + TL) {
        int l = tid - SL;
        float pw = (float)pow((double)1.5f, (double)l);
        rest[l] = floorf(16.0f * pw);
    }
    __syncthreads();

    const int base = blockIdx.x * P;

    // ------------------------------------------------------------------ encode
    for (int task = tid; task < P * NSLOT; task += NT) {
        int p = task / NSLOT;
        int s = task % NSLOT;
        int pi = base + p;
        if (pi >= B) pi = B - 1;  // clamp (B divisible by P anyway)
        float4 c = __ldg(&coords[pi]);
        if (s < SL) {
            float r = ress[s];
            float x = c.x * r, y = c.y * r, z = c.z * r;
            float fx = floorf(x), fy = floorf(y), fz = floorf(z);
            float wx = x - fx, wy = y - fy, wz = z - fz;
            unsigned ux = (unsigned)fx, uy = (unsigned)fy, uz = (unsigned)fz;
            const float2* tb = stab + (size_t)s * SENT;
            float a0 = 0.f, a1 = 0.f;
#pragma unroll
            for (int ci = 0; ci < 8; ci++) {
                unsigned bx = ci & 1u, by = (ci >> 1) & 1u, bz = (ci >> 2) & 1u;
                unsigned h = ((ux + bx) * 1u)
                           ^ ((uy + by) * 2654435761u)
                           ^ ((uz + bz) * 805459861u);
                h &= SMASK;
                float2 f = __ldg(&tb[h]);
                float cw = (bx ? wx : 1.f - wx) * (by ? wy : 1.f - wy);
                cw = cw * (bz ? wz : 1.f - wz);
                a0 += f.x * cw;
                a1 += f.y * cw;
            }
            featsm[2 * s][p]     = a0;
            featsm[2 * s + 1][p] = a1;
        } else {
            int l = s - SL;
            float r  = rest[l];
            float tx = c.w * r;
            float tf = floorf(tx);
            float tw = tx - tf;
            unsigned t0 = (unsigned)tf;
            unsigned i0 = t0 & TMASK;
            unsigned i1 = (t0 + 1u) & TMASK;
            const float2* tb = ttab + (size_t)l * TENT;
            float2 f0 = __ldg(&tb[i0]);
            float2 f1 = __ldg(&tb[i1]);
            featsm[2 * SL + 2 * l][p]     = f0.x * (1.f - tw) + f1.x * tw;
            featsm[2 * SL + 2 * l + 1][p] = f0.y * (1.f - tw) + f1.y * tw;
        }
    }
    __syncthreads();

    // ------------------------------------------------------------------ layer 1
    const int j = tid;  // hidden unit owned by this thread
    float acc[P];
#pragma unroll
    for (int p = 0; p < P; p++) acc[p] = 0.f;

    for (int k = 0; k < ENC; k++) {
        float wv = __ldg(&w1[k * HID + j]);
        float4 fa = *(const float4*)&featsm[k][0];
        float4 fb = *(const float4*)&featsm[k][4];
        acc[0] = fmaf(fa.x, wv, acc[0]);
        acc[1] = fmaf(fa.y, wv, acc[1]);
        acc[2] = fmaf(fa.z, wv, acc[2]);
        acc[3] = fmaf(fa.w, wv, acc[3]);
        acc[4] = fmaf(fb.x, wv, acc[4]);
        acc[5] = fmaf(fb.y, wv, acc[5]);
        acc[6] = fmaf(fb.z, wv, acc[6]);
        acc[7] = fmaf(fb.w, wv, acc[7]);
    }

    {
        float b1j = __ldg(&b1[j]), g1j = __ldg(&g1[j]), be1j = __ldg(&beta1[j]);
        float h[P];
        float sums[2 * P];
#pragma unroll
        for (int p = 0; p < P; p++) {
            float v = fmaxf(acc[p] + b1j, 0.f);
            h[p] = v;
            sums[p]     = v;
            sums[P + p] = v * v;
        }
        block_reduce<2 * P>(sums, red, tid);
#pragma unroll
        for (int p = 0; p < P; p++) {
            float m   = sums[p] * (1.f / HID);
            float var = sums[P + p] * (1.f / HID) - m * m;
            float hn  = (h[p] - m) * rsqrtf(var + 1e-5f) * g1j + be1j;
            h1sm[j][p] = hn;
        }
    }
    __syncthreads();

    // ------------------------------------------------------------------ layer 2
#pragma unroll
    for (int p = 0; p < P; p++) acc[p] = 0.f;

    for (int k = 0; k < HID; k++) {
        float wv = __ldg(&w2[k * HID + j]);
        float4 fa = *(const float4*)&h1sm[k][0];
        float4 fb = *(const float4*)&h1sm[k][4];
        acc[0] = fmaf(fa.x, wv, acc[0]);
        acc[1] = fmaf(fa.y, wv, acc[1]);
        acc[2] = fmaf(fa.z, wv, acc[2]);
        acc[3] = fmaf(fa.w, wv, acc[3]);
        acc[4] = fmaf(fb.x, wv, acc[4]);
        acc[5] = fmaf(fb.y, wv, acc[5]);
        acc[6] = fmaf(fb.z, wv, acc[6]);
        acc[7] = fmaf(fb.w, wv, acc[7]);
    }

    float h2n[P];
    {
        float b2j = __ldg(&b2[j]), g2j = __ldg(&g2[j]), be2j = __ldg(&beta2[j]);
        float h[P];
        float sums[2 * P];
#pragma unroll
        for (int p = 0; p < P; p++) {
            float v = fmaxf(acc[p] + b2j, 0.f);
            h[p] = v;
            sums[p]     = v;
            sums[P + p] = v * v;
        }
        block_reduce<2 * P>(sums, red, tid);
#pragma unroll
        for (int p = 0; p < P; p++) {
            float m   = sums[p] * (1.f / HID);
            float var = sums[P + p] * (1.f / HID) - m * m;
            h2n[p] = (h[p] - m) * rsqrtf(var + 1e-5f) * g2j + be2j;
        }
    }

    // ------------------------------------------------------------------ layer 3
    {
        float w3j = __ldg(&w3[j]);
        float ov[P];
#pragma unroll
        for (int p = 0; p < P; p++) ov[p] = h2n[p] * w3j;
        block_reduce<P>(ov, red, tid);
        if (tid == 0) {
            float bb = __ldg(&b3[0]);
#pragma unroll
            for (int p = 0; p < P; p++) {
                int pi = base + p;
                if (pi < B) out[pi] = ov[p] + bb;
            }
        }
    }
}

extern "C" void kernel_launch(void* const* d_in, const int* in_sizes, int n_in,
                              void* d_out, int out_size) {
    const float4* coords = (const float4*)d_in[0];
    const float2* stab   = (const float2*)d_in[1];
    const float2* ttab   = (const float2*)d_in[2];
    const float*  w1     = (const float*)d_in[3];
    const float*  b1     = (const float*)d_in[4];
    const float*  g1     = (const float*)d_in[5];
    const float*  be1    = (const float*)d_in[6];
    const float*  w2     = (const float*)d_in[7];
    const float*  b2     = (const float*)d_in[8];
    const float*  g2     = (const float*)d_in[9];
    const float*  be2    = (const float*)d_in[10];
    const float*  w3     = (const float*)d_in[11];
    const float*  b3     = (const float*)d_in[12];
    float* out = (float*)d_out;

    int B = in_sizes[0] / 4;
    int blocks = (B + P - 1) / P;
    earth4d_fused_kernel<<<blocks, NT>>>(coords, stab, ttab,
                                         w1, b1, g1, be1,
                                         w2, b2, g2, be2,
                                         w3, b3, out, B);
}

// round 2
// speedup vs baseline: 1.2185x; 1.2185x over previous
#include <cuda_runtime.h>
#include <math.h>

typedef unsigned long long ull;

#define SL 36
#define TL 20
#define SENT (1u << 19)
#define TENT (1u << 17)
#define SMASK (SENT - 1u)
#define TMASK (TENT - 1u)
#define HID 128
#define ENC 112
#define P 32            // points per block
#define NT 128          // threads per block
#define RS 36           // smem row stride (floats), 16B-aligned rows, bank-skewed

// ---- packed fp32x2 helpers (sm_103a FFMA2 path) -----------------------------
__device__ __forceinline__ ull splat2(float v) {
    ull r; asm("mov.b64 %0, {%1, %1};" : "=l"(r) : "f"(v)); return r;
}
__device__ __forceinline__ ull pack2(float a, float b) {
    ull r; asm("mov.b64 %0, {%1, %2};" : "=l"(r) : "f"(a), "f"(b)); return r;
}
__device__ __forceinline__ float2 unpack2(ull v) {
    float2 r; asm("mov.b64 {%0, %1}, %2;" : "=f"(r.x), "=f"(r.y) : "l"(v)); return r;
}
__device__ __forceinline__ ull fma2(ull a, ull b, ull c) {
    ull d; asm("fma.rn.f32x2 %0, %1, %2, %3;" : "=l"(d) : "l"(a), "l"(b), "l"(c)); return d;
}
__device__ __forceinline__ ull mul2(ull a, ull b) {
    ull d; asm("mul.rn.f32x2 %0, %1, %2;" : "=l"(d) : "l"(a), "l"(b)); return d;
}

// ---------------------------------------------------------------------------
// One MLP layer: y = LN(relu(x @ W + b)) for 32 points, K input dims.
// Thread tile: 4 j (j0..j0+3) x 8 p (p0..p0+7). Warp covers 32 j x 32 p.
// buf holds x as [K][RS]; output written back to buf rows 0..127 if WRITE.
// red: float[2*P*4] scratch for cross-warp LN stats.
// ---------------------------------------------------------------------------
template <int K, bool WRITE>
__device__ __forceinline__ void mlp_layer(const float* __restrict__ W,
                                          const float* __restrict__ bias,
                                          const float* __restrict__ g,
                                          const float* __restrict__ beta,
                                          float* buf, float* red,
                                          int j0, int p0, int w, int tj,
                                          float outn[4][8])
{
    ull acc[4][4];
#pragma unroll
    for (int a = 0; a < 4; a++)
#pragma unroll
        for (int q = 0; q < 4; q++) acc[a][q] = 0ull;

#pragma unroll 4
    for (int k = 0; k < K; k++) {
        float4 wv = __ldg((const float4*)(W + k * HID + j0));
        const float4* fr = (const float4*)(buf + k * RS + p0);
        float4 fA = fr[0];
        float4 fB = fr[1];
        ull q0 = pack2(fA.x, fA.y), q1 = pack2(fA.z, fA.w);
        ull q2 = pack2(fB.x, fB.y), q3 = pack2(fB.z, fB.w);
        ull s;
        s = splat2(wv.x);
        acc[0][0] = fma2(q0, s, acc[0][0]); acc[0][1] = fma2(q1, s, acc[0][1]);
        acc[0][2] = fma2(q2, s, acc[0][2]); acc[0][3] = fma2(q3, s, acc[0][3]);
        s = splat2(wv.y);
        acc[1][0] = fma2(q0, s, acc[1][0]); acc[1][1] = fma2(q1, s, acc[1][1]);
        acc[1][2] = fma2(q2, s, acc[1][2]); acc[1][3] = fma2(q3, s, acc[1][3]);
        s = splat2(wv.z);
        acc[2][0] = fma2(q0, s, acc[2][0]); acc[2][1] = fma2(q1, s, acc[2][1]);
        acc[2][2] = fma2(q2, s, acc[2][2]); acc[2][3] = fma2(q3, s, acc[2][3]);
        s = splat2(wv.w);
        acc[3][0] = fma2(q0, s, acc[3][0]); acc[3][1] = fma2(q1, s, acc[3][1]);
        acc[3][2] = fma2(q2, s, acc[3][2]); acc[3][3] = fma2(q3, s, acc[3][3]);
    }

    // bias + relu + per-point partial stats
    float4 bv = __ldg((const float4*)(bias + j0));
    float bb[4] = {bv.x, bv.y, bv.z, bv.w};
    float s1[8], s2[8];
#pragma unroll
    for (int p = 0; p < 8; p++) { s1[p] = 0.f; s2[p] = 0.f; }
#pragma unroll
    for (int a = 0; a < 4; a++) {
#pragma unroll
        for (int q = 0; q < 4; q++) {
            float2 vv = unpack2(acc[a][q]);
            float v0 = fmaxf(vv.x + bb[a], 0.f);
            float v1 = fmaxf(vv.y + bb[a], 0.f);
            outn[a][2 * q]     = v0;
            outn[a][2 * q + 1] = v1;
            s1[2 * q]     += v0; s2[2 * q]     += v0 * v0;
            s1[2 * q + 1] += v1; s2[2 * q + 1] += v1 * v1;
        }
    }
    // reduce over tj (8 lanes sharing these 8 points within the warp)
#pragma unroll
    for (int o = 1; o < 8; o <<= 1) {
#pragma unroll
        for (int p = 0; p < 8; p++) {
            s1[p] += __shfl_xor_sync(0xffffffffu, s1[p], o);
            s2[p] += __shfl_xor_sync(0xffffffffu, s2[p], o);
        }
    }
    if (tj == 0) {
#pragma unroll
        for (int p = 0; p < 8; p++) {
            red[(0 * P + p0 + p) * 4 + w] = s1[p];
            red[(1 * P + p0 + p) * 4 + w] = s2[p];
        }
    }
    __syncthreads();

    float4 gv  = __ldg((const float4*)(g + j0));
    float4 btv = __ldg((const float4*)(beta + j0));
    float gg[4] = {gv.x, gv.y, gv.z, gv.w};
    float bt[4] = {btv.x, btv.y, btv.z, btv.w};
#pragma unroll
    for (int p = 0; p < 8; p++) {
        const float* r0 = &red[(0 * P + p0 + p) * 4];
        const float* r1 = &red[(1 * P + p0 + p) * 4];
        float S1 = (r0[0] + r0[1]) + (r0[2] + r0[3]);
        float S2 = (r1[0] + r1[1]) + (r1[2] + r1[3]);
        float m   = S1 * (1.f / HID);
        float var = S2 * (1.f / HID) - m * m;
        float rs  = rsqrtf(var + 1e-5f);
#pragma unroll
        for (int a = 0; a < 4; a++)
            outn[a][p] = (outn[a][p] - m) * rs * gg[a] + bt[a];
    }
    if (WRITE) {
#pragma unroll
        for (int a = 0; a < 4; a++) {
            float* row = buf + (j0 + a) * RS + p0;
            ((float4*)row)[0] = make_float4(outn[a][0], outn[a][1], outn[a][2], outn[a][3]);
            ((float4*)row)[1] = make_float4(outn[a][4], outn[a][5], outn[a][6], outn[a][7]);
        }
    }
    __syncthreads();
}

__global__ __launch_bounds__(NT)
void earth4d_fused_kernel(const float4* __restrict__ coords,
                          const float2* __restrict__ stab,
                          const float2* __restrict__ ttab,
                          const float*  __restrict__ w1,
                          const float*  __restrict__ b1,
                          const float*  __restrict__ g1,
                          const float*  __restrict__ beta1,
                          const float*  __restrict__ w2,
                          const float*  __restrict__ b2,
                          const float*  __restrict__ g2,
                          const float*  __restrict__ beta2,
                          const float*  __restrict__ w3,
                          const float*  __restrict__ b3,
                          float* __restrict__ out, int B)
{
    __shared__ float ress[SL + TL];
    __shared__ __align__(16) float buf[HID * RS];   // feats (112 rows) -> h1 (128 rows)
    __shared__ float red[2 * P * 4];
    __shared__ float red3[4 * P];

    const int tid  = threadIdx.x;
    const int w    = tid >> 5;
    const int lane = tid & 31;

    // per-level resolutions: correctly-rounded fp32 pow via double
    if (tid < SL) {
        ress[tid] = floorf(16.0f * (float)pow((double)1.38f, (double)tid));
    } else if (tid < SL + TL) {
        ress[tid] = floorf(16.0f * (float)pow((double)1.5f, (double)(tid - SL)));
    }
    __syncthreads();

    const int base = blockIdx.x * P;
    int pi = base + lane;
    if (pi >= B) pi = B - 1;
    const float4 c = __ldg(&coords[pi]);

    // ---------------------------------------------------------------- encode
    // lane = point, warp-uniform level: warp w handles s = 4*i + w
#pragma unroll 1
    for (int i = 0; i < 14; i++) {
        int s = i * 4 + w;
        if (s < SL) {
            float r = ress[s];
            float x = c.x * r, y = c.y * r, z = c.z * r;
            float fx = floorf(x), fy = floorf(y), fz = floorf(z);
            float wx = x - fx, wy = y - fy, wz = z - fz;
            float mx = 1.f - wx, my = 1.f - wy, mz = 1.f - wz;
            unsigned ux = (unsigned)fx, uy = (unsigned)fy, uz = (unsigned)fz;
            unsigned hx0 = ux, hx1 = ux + 1u;
            unsigned hy0 = uy * 2654435761u, hy1 = (uy + 1u) * 2654435761u;
            unsigned hz0 = uz * 805459861u,  hz1 = (uz + 1u) * 805459861u;
            float mymz = my * mz, wymz = wy * mz, mywz = my * wz, wywz = wy * wz;
            const float2* tb = stab + (size_t)s * SENT;
            ull acc = 0ull;
#define CORNER(HX, HY, HZ, CW) { \
            unsigned hh = ((HX) ^ (HY) ^ (HZ)) & SMASK; \
            ull f = *(const ull*)(tb + hh); \
            acc = fma2(f, splat2(CW), acc); }
            CORNER(hx0, hy0, hz0, mx * mymz)
            CORNER(hx1, hy0, hz0, wx * mymz)
            CORNER(hx0, hy1, hz0, mx * wymz)
            CORNER(hx1, hy1, hz0, wx * wymz)
            CORNER(hx0, hy0, hz1, mx * mywz)
            CORNER(hx1, hy0, hz1, wx * mywz)
            CORNER(hx0, hy1, hz1, mx * wywz)
            CORNER(hx1, hy1, hz1, wx * wywz)
#undef CORNER
            float2 a = unpack2(acc);
            buf[(2 * s) * RS + lane]     = a.x;
            buf[(2 * s + 1) * RS + lane] = a.y;
        } else {
            int l = s - SL;
            float r  = ress[s];
            float tx = c.w * r;
            float tf = floorf(tx);
            float tw = tx - tf;
            unsigned t0 = (unsigned)tf;
            const float2* tb = ttab + (size_t)l * TENT;
            ull f0 = *(const ull*)(tb + (t0 & TMASK));
            ull f1 = *(const ull*)(tb + ((t0 + 1u) & TMASK));
            ull acc = mul2(f0, splat2(1.f - tw));
            acc = fma2(f1, splat2(tw), acc);
            float2 a = unpack2(acc);
            buf[(2 * SL + 2 * l) * RS + lane]     = a.x;
            buf[(2 * SL + 2 * l + 1) * RS + lane] = a.y;
        }
    }
    __syncthreads();

    // ---------------------------------------------------------------- MLP
    const int tj = lane & 7;
    const int tp = lane >> 3;
    const int j0 = w * 32 + tj * 4;
    const int p0 = tp * 8;

    float h[4][8];
    mlp_layer<ENC, true >(w1, b1, g1, beta1, buf, red, j0, p0, w, tj, h);
    mlp_layer<HID, false>(w2, b2, g2, beta2, buf, red, j0, p0, w, tj, h);

    // ---------------------------------------------------------------- layer 3
    {
        float4 w3v = __ldg((const float4*)(w3 + j0));
        float part[8];
#pragma unroll
        for (int p = 0; p < 8; p++)
            part[p] = h[0][p] * w3v.x + h[1][p] * w3v.y
                    + h[2][p] * w3v.z + h[3][p] * w3v.w;
#pragma unroll
        for (int o = 1; o < 8; o <<= 1)
#pragma unroll
            for (int p = 0; p < 8; p++)
                part[p] += __shfl_xor_sync(0xffffffffu, part[p], o);
        if (tj == 0) {
#pragma unroll
            for (int p = 0; p < 8; p++)
                red3[w * P + p0 + p] = part[p];
        }
        __syncthreads();
        if (tid < P) {
            float o = red3[0 * P + tid] + red3[1 * P + tid]
                    + red3[2 * P + tid] + red3[3 * P + tid] + __ldg(&b3[0]);
            int po = base + tid;
            if (po < B) out[po] = o;
        }
    }
}

extern "C" void kernel_launch(void* const* d_in, const int* in_sizes, int n_in,
                              void* d_out, int out_size) {
    const float4* coords = (const float4*)d_in[0];
    const float2* stab   = (const float2*)d_in[1];
    const float2* ttab   = (const float2*)d_in[2];
    const float*  w1     = (const float*)d_in[3];
    const float*  b1     = (const float*)d_in[4];
    const float*  g1     = (const float*)d_in[5];
    const float*  be1    = (const float*)d_in[6];
    const float*  w2     = (const float*)d_in[7];
    const float*  b2     = (const float*)d_in[8];
    const float*  g2     = (const float*)d_in[9];
    const float*  be2    = (const float*)d_in[10];
    const float*  w3     = (const float*)d_in[11];
    const float*  b3     = (const float*)d_in[12];
    float* out = (float*)d_out;

    int B = in_sizes[0] / 4;
    int blocks = (B + P - 1) / P;
    earth4d_fused_kernel<<<blocks, NT>>>(coords, stab, ttab,
                                         w1, b1, g1, be1,
                                         w2, b2, g2, be2,
                                         w3, b3, out, B);
}